// round 8
// baseline (speedup 1.0000x reference)
#include <cuda_runtime.h>
#include <cuda_bf16.h>
#include <cstdint>

#define T_DIM 512
#define B_DIM 128
#define E_DIM 256
#define U_DIM 256

// Scratch for xW[t][b][u]  (64 MB fp32 — L2-resident)
__device__ float g_xw[T_DIM * B_DIM * U_DIM];

// ---------------- helpers ----------------
__device__ __forceinline__ uint32_t smem_u32(const void* p) {
    uint32_t a;
    asm("{ .reg .u64 t; cvta.to.shared.u64 t, %1; cvt.u32.u64 %0, t; }" : "=r"(a) : "l"(p));
    return a;
}
__device__ __forceinline__ uint32_t packbf(float a, float b) {
    __nv_bfloat162 t = __floats2bfloat162_rn(a, b);   // .x -> low 16, .y -> high 16
    return *reinterpret_cast<uint32_t*>(&t);
}
__device__ __forceinline__ float blo(uint32_t v) { return __uint_as_float(v << 16); }

__device__ __forceinline__ void ldsm_x4(uint32_t* r, uint32_t addr) {
    asm volatile("ldmatrix.sync.aligned.m8n8.x4.shared.b16 {%0,%1,%2,%3}, [%4];"
                 : "=r"(r[0]), "=r"(r[1]), "=r"(r[2]), "=r"(r[3]) : "r"(addr));
}
__device__ __forceinline__ void ldsm_x2(uint32_t* r, uint32_t addr) {
    asm volatile("ldmatrix.sync.aligned.m8n8.x2.shared.b16 {%0,%1}, [%2];"
                 : "=r"(r[0]), "=r"(r[1]) : "r"(addr));
}
__device__ __forceinline__ void mma_bf16(float* c, const uint32_t* a, const uint32_t* b) {
    asm volatile("mma.sync.aligned.m16n8k16.row.col.f32.bf16.bf16.f32 "
                 "{%0,%1,%2,%3}, {%4,%5,%6,%7}, {%8,%9}, {%0,%1,%2,%3};"
                 : "+f"(c[0]), "+f"(c[1]), "+f"(c[2]), "+f"(c[3])
                 : "r"(a[0]), "r"(a[1]), "r"(a[2]), "r"(a[3]), "r"(b[0]), "r"(b[1]));
}

// ---------------- Kernel 1: xW[t][b][u] = emb[token(b,t)] . W[u] ----------------
// One CTA per timestep t (512 CTAs, 256 threads / 8 warps), bf16 HMMA.

static constexpr int APAD = 264;                     // bf16 elems per smem row
static constexpr int AS_OFF = 0;
static constexpr int BS_OFF = 128 * APAD * 2;        // 67584
static constexpr int XW_SMEM = BS_OFF + 256 * APAD * 2;  // 202752

__global__ void __launch_bounds__(256, 1)
xw_kernel(const int* __restrict__ sentence, const float* __restrict__ emb,
          const float* __restrict__ W) {
    extern __shared__ char smem[];
    const int tid = threadIdx.x, t = blockIdx.x;
    const int wid = tid >> 5, lane = tid & 31;
    const uint32_t sb = smem_u32(smem);

    // stage A (emb rows of this timestep's tokens)
    {
        const int sub = tid & 7;
        #pragma unroll
        for (int p = 0; p < 4; p++) {
            const int r = p * 32 + (tid >> 3);
            const int tok = sentence[r * T_DIM + t];
            const float4* src = reinterpret_cast<const float4*>(emb + (size_t)tok * E_DIM) + sub;
            char* dstrow = smem + AS_OFF + r * (APAD * 2);
            #pragma unroll
            for (int j = 0; j < 8; j++) {
                float4 v = src[j * 8];
                *reinterpret_cast<uint2*>(dstrow + (sub + j * 8) * 8) =
                    make_uint2(packbf(v.x, v.y), packbf(v.z, v.w));
            }
        }
    }
    // stage B (W rows)
    {
        const int sub = tid & 7;
        #pragma unroll
        for (int p = 0; p < 8; p++) {
            const int r = p * 32 + (tid >> 3);
            const float4* src = reinterpret_cast<const float4*>(W + (size_t)r * E_DIM) + sub;
            char* dstrow = smem + BS_OFF + r * (APAD * 2);
            #pragma unroll
            for (int j = 0; j < 8; j++) {
                float4 v = src[j * 8];
                *reinterpret_cast<uint2*>(dstrow + (sub + j * 8) * 8) =
                    make_uint2(packbf(v.x, v.y), packbf(v.z, v.w));
            }
        }
    }
    __syncthreads();

    const int m0 = wid * 16;
    float c[32][4];
    #pragma unroll
    for (int j = 0; j < 32; j++) { c[j][0] = c[j][1] = c[j][2] = c[j][3] = 0.f; }

    const uint32_t a_addr = sb + AS_OFF + (m0 + (lane & 15)) * (APAD * 2) + (lane >> 4) * 16;
    const uint32_t b_addr = sb + BS_OFF + (lane & 7) * (APAD * 2) + ((lane >> 3) & 1) * 16;

    for (int k = 0; k < 16; k++) {
        uint32_t a[4];
        ldsm_x4(a, a_addr + k * 32);
        #pragma unroll
        for (int j = 0; j < 32; j++) {
            uint32_t b[2];
            ldsm_x2(b, b_addr + j * 8 * (APAD * 2) + k * 32);
            mma_bf16(c[j], a, b);
        }
    }

    float* outp = g_xw + (size_t)t * (B_DIM * U_DIM);
    const int r0 = m0 + (lane >> 2), c0 = (lane & 3) * 2;
    #pragma unroll
    for (int j = 0; j < 32; j++) {
        const int col = j * 8 + c0;
        *reinterpret_cast<float2*>(outp + r0 * U_DIM + col)       = make_float2(c[j][0], c[j][1]);
        *reinterpret_cast<float2*>(outp + (r0 + 8) * U_DIM + col) = make_float2(c[j][2], c[j][3]);
    }
}

// ---------------- Kernel 2: recurrence + head ----------------
// 128 CTAs, 1024 threads. Tile (2 u x 32 k) per thread:
//   g = tid>>3 owns units {2g, 2g+1}; lane p = tid&7 owns k in [32p, 32p+32).
// U as 32 bf16x2 regs (dirty-hi for odd k). h-loads dedup within the warp
// (4 g-groups read identical addresses -> 1 wavefront per LDS.128).
// Reduction: value-merged 3-round shfl (3 shfl + 3 FADD + 2 SEL) inside each octet.
// xw prefetched one step ahead on lanes p<2.

__global__ void __launch_bounds__(1024, 1)
rnn_kernel(const float* __restrict__ Um, const float* __restrict__ W1,
           const float* __restrict__ b1, const float* __restrict__ W2,
           const float* __restrict__ b2, float* __restrict__ out) {
    __shared__ float h[512 + 32];
    float* hid = h + 512;
    const int tid = threadIdx.x;
    const int b   = blockIdx.x;
    const int g   = tid >> 3;        // u-pair: units 2g, 2g+1
    const int p   = tid & 7;         // k-block [32p, 32p+32)

    // one-time: U rows 2g, 2g+1, k-block 32p.. -> 2 x 16 bf16x2 regs
    uint32_t ur0[16], ur1[16];
    {
        const float4* s0 = reinterpret_cast<const float4*>(Um + (size_t)(2 * g) * U_DIM + 32 * p);
        const float4* s1 = reinterpret_cast<const float4*>(Um + (size_t)(2 * g + 1) * U_DIM + 32 * p);
        #pragma unroll
        for (int i = 0; i < 8; i++) {
            float4 v0 = s0[i], v1 = s1[i];
            ur0[2 * i]     = packbf(v0.x, v0.y);
            ur0[2 * i + 1] = packbf(v0.z, v0.w);
            ur1[2 * i]     = packbf(v1.x, v1.y);
            ur1[2 * i + 1] = packbf(v1.z, v1.w);
        }
    }
    if (tid < 256) h[tid] = 0.0f;    // buffer 0 = initial state
    __syncthreads();

    // xw stream: lane p<2 handles unit u = 2g+p
    const float* xwp = g_xw + (size_t)b * U_DIM + 2 * g + p;
    float xw = (p < 2) ? xwp[0] : 0.0f;

    #pragma unroll 2
    for (int t = 0; t < T_DIM; t++) {
        const int tn = (t + 1 < T_DIM) ? t + 1 : t;
        const float xw_n = (p < 2) ? xwp[(size_t)tn * (B_DIM * U_DIM)] : 0.0f;
        const float4* hb4 = reinterpret_cast<const float4*>(h + ((t & 1) << 8)) + 8 * p;

        float a00 = 0.f, a01 = 0.f, a10 = 0.f, a11 = 0.f;
        #pragma unroll
        for (int i = 0; i < 8; i++) {
            float4 hv = hb4[i];                 // 8 distinct addrs/warp -> 1 wf
            const uint32_t r0 = ur0[2 * i], r1 = ur0[2 * i + 1];
            a00 = fmaf(blo(r0), hv.x, a00);
            a01 = fmaf(__uint_as_float(r0), hv.y, a01);  // dirty-hi bf16
            a00 = fmaf(blo(r1), hv.z, a00);
            a01 = fmaf(__uint_as_float(r1), hv.w, a01);
            const uint32_t q0 = ur1[2 * i], q1 = ur1[2 * i + 1];
            a10 = fmaf(blo(q0), hv.x, a10);
            a11 = fmaf(__uint_as_float(q0), hv.y, a11);
            a10 = fmaf(blo(q1), hv.z, a10);
            a11 = fmaf(__uint_as_float(q1), hv.w, a11);
        }
        float s0 = a00 + a01;                  // unit 2g partial
        float s1 = a10 + a11;                  // unit 2g+1 partial
        // value-merged reduce over octet (xor 1: merge u0/u1; xor 2,4: finish)
        float tv = (p & 1) ? s1 : s0;
        float ov = (p & 1) ? s0 : s1;
        tv += __shfl_xor_sync(0xffffffffu, ov, 1);
        tv += __shfl_xor_sync(0xffffffffu, tv, 2);
        tv += __shfl_xor_sync(0xffffffffu, tv, 4);
        if (p < 2) {                           // lane0 -> u=2g, lane1 -> u=2g+1
            float r = tv + xw;
            float hn;
            asm("tanh.approx.f32 %0, %1;" : "=f"(hn) : "f"(r));
            h[(((t & 1) ^ 1) << 8) + 2 * g + p] = hn;
        }
        xw = xw_n;
        __syncthreads();
    }

    // Head: final h in buffer 0 (t=511 wrote buffer 0)
    const float* hf = h;
    if (tid < 32) {
        float a = b1[tid];
        #pragma unroll 8
        for (int k = 0; k < 256; k++) a += hf[k] * W1[k * 32 + tid];
        hid[tid] = fmaxf(a, 0.0f);
    }
    __syncthreads();
    if (tid == 0) {
        float l0 = b2[0], l1 = b2[1];
        #pragma unroll
        for (int j = 0; j < 32; j++) {
            float x = hid[j];
            l0 += x * W2[j * 2 + 0];
            l1 += x * W2[j * 2 + 1];
        }
        float mx = fmaxf(l0, l1);
        float e0 = __expf(l0 - mx), e1 = __expf(l1 - mx);
        float inv = 1.0f / (e0 + e1);
        out[b * 2 + 0] = e0 * inv;
        out[b * 2 + 1] = e1 * inv;
    }
}

// ---------------- launch ----------------
extern "C" void kernel_launch(void* const* d_in, const int* in_sizes, int n_in,
                              void* d_out, int out_size) {
    const int*   sentence = (const int*)  d_in[0];
    const float* emb      = (const float*)d_in[1];
    const float* W        = (const float*)d_in[2];
    const float* Um       = (const float*)d_in[3];
    const float* W1       = (const float*)d_in[4];
    const float* b1       = (const float*)d_in[5];
    const float* W2       = (const float*)d_in[6];
    const float* b2       = (const float*)d_in[7];
    float* out = (float*)d_out;

    cudaFuncSetAttribute(xw_kernel, cudaFuncAttributeMaxDynamicSharedMemorySize, XW_SMEM);

    xw_kernel<<<T_DIM, 256, XW_SMEM>>>(sentence, emb, W);
    rnn_kernel<<<B_DIM, 1024>>>(Um, W1, b1, W2, b2, out);
}

// round 9
// speedup vs baseline: 2.6900x; 2.6900x over previous
#include <cuda_runtime.h>
#include <cuda_bf16.h>
#include <cstdint>

#define T_DIM 512
#define B_DIM 128
#define E_DIM 256
#define U_DIM 256

// Scratch for xW[t][b][u]  (64 MB fp32 — L2-resident)
__device__ float g_xw[T_DIM * B_DIM * U_DIM];

// ---------------- helpers ----------------
__device__ __forceinline__ uint32_t smem_u32(const void* p) {
    uint32_t a;
    asm("{ .reg .u64 t; cvta.to.shared.u64 t, %1; cvt.u32.u64 %0, t; }" : "=r"(a) : "l"(p));
    return a;
}
__device__ __forceinline__ uint32_t packbf(float a, float b) {
    __nv_bfloat162 t = __floats2bfloat162_rn(a, b);   // .x -> low 16, .y -> high 16
    return *reinterpret_cast<uint32_t*>(&t);
}
__device__ __forceinline__ void ldsm_x4(uint32_t* r, uint32_t addr) {
    asm volatile("ldmatrix.sync.aligned.m8n8.x4.shared.b16 {%0,%1,%2,%3}, [%4];"
                 : "=r"(r[0]), "=r"(r[1]), "=r"(r[2]), "=r"(r[3]) : "r"(addr));
}
__device__ __forceinline__ void ldsm_x2(uint32_t* r, uint32_t addr) {
    asm volatile("ldmatrix.sync.aligned.m8n8.x2.shared.b16 {%0,%1}, [%2];"
                 : "=r"(r[0]), "=r"(r[1]) : "r"(addr));
}
__device__ __forceinline__ void mma_bf16(float* c, const uint32_t* a, const uint32_t* b) {
    asm volatile("mma.sync.aligned.m16n8k16.row.col.f32.bf16.bf16.f32 "
                 "{%0,%1,%2,%3}, {%4,%5,%6,%7}, {%8,%9}, {%0,%1,%2,%3};"
                 : "+f"(c[0]), "+f"(c[1]), "+f"(c[2]), "+f"(c[3])
                 : "r"(a[0]), "r"(a[1]), "r"(a[2]), "r"(a[3]), "r"(b[0]), "r"(b[1]));
}

// ---------------- Kernel 1: xW[t][b][u] = emb[token(b,t)] . W[u] ----------------
// One CTA per timestep t (512 CTAs, 256 threads / 8 warps), bf16 HMMA.

static constexpr int APAD = 264;                     // bf16 elems per smem row
static constexpr int AS_OFF = 0;
static constexpr int BS_OFF = 128 * APAD * 2;        // 67584
static constexpr int XW_SMEM = BS_OFF + 256 * APAD * 2;  // 202752

__global__ void __launch_bounds__(256, 1)
xw_kernel(const int* __restrict__ sentence, const float* __restrict__ emb,
          const float* __restrict__ W) {
    extern __shared__ char smem[];
    const int tid = threadIdx.x, t = blockIdx.x;
    const int wid = tid >> 5, lane = tid & 31;
    const uint32_t sb = smem_u32(smem);

    // stage A (emb rows of this timestep's tokens)
    {
        const int sub = tid & 7;
        #pragma unroll
        for (int p = 0; p < 4; p++) {
            const int r = p * 32 + (tid >> 3);
            const int tok = sentence[r * T_DIM + t];
            const float4* src = reinterpret_cast<const float4*>(emb + (size_t)tok * E_DIM) + sub;
            char* dstrow = smem + AS_OFF + r * (APAD * 2);
            #pragma unroll
            for (int j = 0; j < 8; j++) {
                float4 v = src[j * 8];
                *reinterpret_cast<uint2*>(dstrow + (sub + j * 8) * 8) =
                    make_uint2(packbf(v.x, v.y), packbf(v.z, v.w));
            }
        }
    }
    // stage B (W rows)
    {
        const int sub = tid & 7;
        #pragma unroll
        for (int p = 0; p < 8; p++) {
            const int r = p * 32 + (tid >> 3);
            const float4* src = reinterpret_cast<const float4*>(W + (size_t)r * E_DIM) + sub;
            char* dstrow = smem + BS_OFF + r * (APAD * 2);
            #pragma unroll
            for (int j = 0; j < 8; j++) {
                float4 v = src[j * 8];
                *reinterpret_cast<uint2*>(dstrow + (sub + j * 8) * 8) =
                    make_uint2(packbf(v.x, v.y), packbf(v.z, v.w));
            }
        }
    }
    __syncthreads();

    const int m0 = wid * 16;
    float c[32][4];
    #pragma unroll
    for (int j = 0; j < 32; j++) { c[j][0] = c[j][1] = c[j][2] = c[j][3] = 0.f; }

    const uint32_t a_addr = sb + AS_OFF + (m0 + (lane & 15)) * (APAD * 2) + (lane >> 4) * 16;
    const uint32_t b_addr = sb + BS_OFF + (lane & 7) * (APAD * 2) + ((lane >> 3) & 1) * 16;

    for (int k = 0; k < 16; k++) {
        uint32_t a[4];
        ldsm_x4(a, a_addr + k * 32);
        #pragma unroll
        for (int j = 0; j < 32; j++) {
            uint32_t b[2];
            ldsm_x2(b, b_addr + j * 8 * (APAD * 2) + k * 32);
            mma_bf16(c[j], a, b);
        }
    }

    float* outp = g_xw + (size_t)t * (B_DIM * U_DIM);
    const int r0 = m0 + (lane >> 2), c0 = (lane & 3) * 2;
    #pragma unroll
    for (int j = 0; j < 32; j++) {
        const int col = j * 8 + c0;
        *reinterpret_cast<float2*>(outp + r0 * U_DIM + col)       = make_float2(c[j][0], c[j][1]);
        *reinterpret_cast<float2*>(outp + (r0 + 8) * U_DIM + col) = make_float2(c[j][2], c[j][3]);
    }
}

// ---------------- Kernel 2: tensor-core recurrence + head ----------------
// 8 CTAs x 16 batch rows, 256 threads (8 warps). Per step:
//   C[16,256] = h_t[16,256] @ U^T  via m16n8k16 HMMA (warp owns 32 n-cols),
//   h_{t+1} = tanh(C + xw_t), converted to bf16, double-buffered in smem.
// U staged once in smem (528B padded rows, ldmatrix conflict-free).
// xw for the current step LDG'd from L2 before the HMMA phase (latency hidden).

static constexpr int R_STRIDE = 528;                    // 264 bf16 per row
static constexpr int R_U_OFF  = 0;                      // 256 rows
static constexpr int R_AB0    = 256 * R_STRIDE;         // 135168
static constexpr int R_ABSZ   = 16 * R_STRIDE;          // 8448
static constexpr int R_AB1    = R_AB0 + R_ABSZ;         // 143616
static constexpr int R_HFIN   = R_AB1 + R_ABSZ;         // 152064 (16x256 fp32)
static constexpr int R_HID    = R_HFIN + 16 * 256 * 4;  // 168448 (16x32 fp32)
static constexpr int RNN_SMEM = R_HID + 16 * 32 * 4;    // 170496

__global__ void __launch_bounds__(256, 1)
rnn_kernel(const float* __restrict__ Um, const float* __restrict__ W1,
           const float* __restrict__ b1, const float* __restrict__ W2,
           const float* __restrict__ b2, float* __restrict__ out) {
    extern __shared__ char smem[];
    const int tid = threadIdx.x, wid = tid >> 5, lane = tid & 31;
    const int b0 = blockIdx.x * 16;                 // batch rows b0..b0+15
    const uint32_t sb = smem_u32(smem);

    // --- stage U (once): row u, 528B stride, bf16 ---
    {
        const int sub = tid & 7;
        #pragma unroll
        for (int p = 0; p < 8; p++) {
            const int r = p * 32 + (tid >> 3);
            const float4* src = reinterpret_cast<const float4*>(Um + (size_t)r * U_DIM) + sub;
            char* dst = smem + R_U_OFF + r * R_STRIDE;
            #pragma unroll
            for (int j = 0; j < 8; j++) {
                float4 v = src[j * 8];
                *reinterpret_cast<uint2*>(dst + (sub + j * 8) * 8) =
                    make_uint2(packbf(v.x, v.y), packbf(v.z, v.w));
            }
        }
    }
    // zero both h buffers (h0 = 0)
    for (int i = tid; i < (2 * R_ABSZ) / 4; i += 256)
        reinterpret_cast<uint32_t*>(smem + R_AB0)[i] = 0;
    __syncthreads();

    const int wcol = wid * 32;
    const int r0 = lane >> 2, q = lane & 3;

    // B (U) ldmatrix addresses per n-tile j: rows wcol+8j+(lane&7), 4x16B k-chunks
    uint32_t b_addr[4];
    #pragma unroll
    for (int j = 0; j < 4; j++)
        b_addr[j] = sb + R_U_OFF + (wcol + j * 8 + (lane & 7)) * R_STRIDE + (lane >> 3) * 16;

    // xw base for (row r0, col wcol + 8j + 2q); +8*U_DIM for row r0+8
    const float* xwbase = g_xw + (size_t)(b0 + r0) * U_DIM + wcol + q * 2;

    for (int t = 0; t < T_DIM; t++) {
        // prefetch this step's xw (L2) — consumed after the HMMA phase
        float2 xv[4][2];
        {
            const float* pt = xwbase + (size_t)t * (B_DIM * U_DIM);
            #pragma unroll
            for (int j = 0; j < 4; j++) {
                xv[j][0] = *reinterpret_cast<const float2*>(pt + j * 8);
                xv[j][1] = *reinterpret_cast<const float2*>(pt + j * 8 + 8 * U_DIM);
            }
        }

        const uint32_t a_base = sb + ((t & 1) ? R_AB1 : R_AB0)
                              + (lane & 15) * R_STRIDE + (lane >> 4) * 16;
        float accL[4][4], accH[4][4];
        #pragma unroll
        for (int j = 0; j < 4; j++)
            #pragma unroll
            for (int i = 0; i < 4; i++) { accL[j][i] = 0.f; accH[j][i] = 0.f; }

        #pragma unroll
        for (int k = 0; k < 8; k++) {               // k32 blocks
            uint32_t alo[4], ahi[4];
            ldsm_x4(alo, a_base + k * 64);          // m16 x k[32k..32k+16)
            ldsm_x4(ahi, a_base + k * 64 + 32);     // m16 x k[32k+16..32k+32)
            #pragma unroll
            for (int j = 0; j < 4; j++) {
                uint32_t bq[4];
                ldsm_x4(bq, b_addr[j] + k * 64);    // n8 x k32
                mma_bf16(accL[j], alo, bq);         // bq[0..1] = k lo16
                mma_bf16(accH[j], ahi, bq + 2);     // bq[2..3] = k hi16
            }
        }

        // epilogue: add xw, tanh, pack bf16, store into NEXT h buffer
        char* an = smem + ((t & 1) ? R_AB0 : R_AB1);
        float* hf = reinterpret_cast<float*>(smem + R_HFIN);
        #pragma unroll
        for (int j = 0; j < 4; j++) {
            const int c0 = wcol + j * 8 + q * 2;
            float s0 = accL[j][0] + accH[j][0] + xv[j][0].x;
            float s1 = accL[j][1] + accH[j][1] + xv[j][0].y;
            float s2 = accL[j][2] + accH[j][2] + xv[j][1].x;
            float s3 = accL[j][3] + accH[j][3] + xv[j][1].y;
            float h0, h1, h2, h3;
            asm("tanh.approx.f32 %0, %1;" : "=f"(h0) : "f"(s0));
            asm("tanh.approx.f32 %0, %1;" : "=f"(h1) : "f"(s1));
            asm("tanh.approx.f32 %0, %1;" : "=f"(h2) : "f"(s2));
            asm("tanh.approx.f32 %0, %1;" : "=f"(h3) : "f"(s3));
            *reinterpret_cast<uint32_t*>(an + r0 * R_STRIDE + c0 * 2)       = packbf(h0, h1);
            *reinterpret_cast<uint32_t*>(an + (r0 + 8) * R_STRIDE + c0 * 2) = packbf(h2, h3);
            if (t == T_DIM - 1) {                    // fp32 copy for the head
                hf[r0 * 256 + c0] = h0;  hf[r0 * 256 + c0 + 1] = h1;
                hf[(r0 + 8) * 256 + c0] = h2;  hf[(r0 + 8) * 256 + c0 + 1] = h3;
            }
        }
        __syncthreads();
    }

    // ---- head: hidden = relu(hfin @ W1 + b1); logits -> softmax ----
    const float* hf = reinterpret_cast<const float*>(smem + R_HFIN);
    float* hid = reinterpret_cast<float*>(smem + R_HID);
    #pragma unroll
    for (int it = 0; it < 2; it++) {
        const int idx = tid + it * 256;   // 512 slots = 16 rows x 32 units
        const int r = idx >> 5, j = idx & 31;
        float a = b1[j];
        #pragma unroll 8
        for (int k = 0; k < 256; k++) a = fmaf(hf[r * 256 + k], W1[k * 32 + j], a);
        hid[r * 32 + j] = fmaxf(a, 0.0f);
    }
    __syncthreads();
    if (tid < 16) {
        float l0 = b2[0], l1 = b2[1];
        #pragma unroll
        for (int j = 0; j < 32; j++) {
            float x = hid[tid * 32 + j];
            l0 += x * W2[j * 2 + 0];
            l1 += x * W2[j * 2 + 1];
        }
        float mx = fmaxf(l0, l1);
        float e0 = __expf(l0 - mx), e1 = __expf(l1 - mx);
        float inv = 1.0f / (e0 + e1);
        out[(b0 + tid) * 2 + 0] = e0 * inv;
        out[(b0 + tid) * 2 + 1] = e1 * inv;
    }
}

// ---------------- launch ----------------
extern "C" void kernel_launch(void* const* d_in, const int* in_sizes, int n_in,
                              void* d_out, int out_size) {
    const int*   sentence = (const int*)  d_in[0];
    const float* emb      = (const float*)d_in[1];
    const float* W        = (const float*)d_in[2];
    const float* Um       = (const float*)d_in[3];
    const float* W1       = (const float*)d_in[4];
    const float* b1       = (const float*)d_in[5];
    const float* W2       = (const float*)d_in[6];
    const float* b2       = (const float*)d_in[7];
    float* out = (float*)d_out;

    cudaFuncSetAttribute(xw_kernel,  cudaFuncAttributeMaxDynamicSharedMemorySize, XW_SMEM);
    cudaFuncSetAttribute(rnn_kernel, cudaFuncAttributeMaxDynamicSharedMemorySize, RNN_SMEM);

    xw_kernel<<<T_DIM, 256, XW_SMEM>>>(sentence, emb, W);
    rnn_kernel<<<B_DIM / 16, 256, RNN_SMEM>>>(Um, W1, b1, W2, b2, out);
}

// round 10
// speedup vs baseline: 3.9558x; 1.4706x over previous
#include <cuda_runtime.h>
#include <cuda_bf16.h>
#include <cstdint>

#define T_DIM 512
#define B_DIM 128
#define E_DIM 256
#define U_DIM 256

// Scratch for xW[t][b][u]  (64 MB fp32 — L2-resident)
__device__ float g_xw[T_DIM * B_DIM * U_DIM];

// ---------------- helpers ----------------
__device__ __forceinline__ uint32_t smem_u32(const void* p) {
    uint32_t a;
    asm("{ .reg .u64 t; cvta.to.shared.u64 t, %1; cvt.u32.u64 %0, t; }" : "=r"(a) : "l"(p));
    return a;
}
__device__ __forceinline__ uint32_t packbf(float a, float b) {
    __nv_bfloat162 t = __floats2bfloat162_rn(a, b);   // .x -> low 16, .y -> high 16
    return *reinterpret_cast<uint32_t*>(&t);
}
__device__ __forceinline__ void ldsm_x4(uint32_t* r, uint32_t addr) {
    asm volatile("ldmatrix.sync.aligned.m8n8.x4.shared.b16 {%0,%1,%2,%3}, [%4];"
                 : "=r"(r[0]), "=r"(r[1]), "=r"(r[2]), "=r"(r[3]) : "r"(addr));
}
__device__ __forceinline__ void ldsm_x2(uint32_t* r, uint32_t addr) {
    asm volatile("ldmatrix.sync.aligned.m8n8.x2.shared.b16 {%0,%1}, [%2];"
                 : "=r"(r[0]), "=r"(r[1]) : "r"(addr));
}
__device__ __forceinline__ void mma_bf16(float* c, const uint32_t* a, const uint32_t* b) {
    asm volatile("mma.sync.aligned.m16n8k16.row.col.f32.bf16.bf16.f32 "
                 "{%0,%1,%2,%3}, {%4,%5,%6,%7}, {%8,%9}, {%0,%1,%2,%3};"
                 : "+f"(c[0]), "+f"(c[1]), "+f"(c[2]), "+f"(c[3])
                 : "r"(a[0]), "r"(a[1]), "r"(a[2]), "r"(a[3]), "r"(b[0]), "r"(b[1]));
}

// ---------------- Kernel 1: xW[t][b][u] = emb[token(b,t)] . W[u] ----------------
// One CTA per timestep t (512 CTAs, 256 threads / 8 warps), bf16 HMMA.

static constexpr int APAD = 264;                     // bf16 elems per smem row
static constexpr int AS_OFF = 0;
static constexpr int BS_OFF = 128 * APAD * 2;        // 67584
static constexpr int XW_SMEM = BS_OFF + 256 * APAD * 2;  // 202752

__global__ void __launch_bounds__(256, 1)
xw_kernel(const int* __restrict__ sentence, const float* __restrict__ emb,
          const float* __restrict__ W) {
    extern __shared__ char smem[];
    const int tid = threadIdx.x, t = blockIdx.x;
    const int wid = tid >> 5, lane = tid & 31;
    const uint32_t sb = smem_u32(smem);

    {
        const int sub = tid & 7;
        #pragma unroll
        for (int p = 0; p < 4; p++) {
            const int r = p * 32 + (tid >> 3);
            const int tok = sentence[r * T_DIM + t];
            const float4* src = reinterpret_cast<const float4*>(emb + (size_t)tok * E_DIM) + sub;
            char* dstrow = smem + AS_OFF + r * (APAD * 2);
            #pragma unroll
            for (int j = 0; j < 8; j++) {
                float4 v = src[j * 8];
                *reinterpret_cast<uint2*>(dstrow + (sub + j * 8) * 8) =
                    make_uint2(packbf(v.x, v.y), packbf(v.z, v.w));
            }
        }
    }
    {
        const int sub = tid & 7;
        #pragma unroll
        for (int p = 0; p < 8; p++) {
            const int r = p * 32 + (tid >> 3);
            const float4* src = reinterpret_cast<const float4*>(W + (size_t)r * E_DIM) + sub;
            char* dstrow = smem + BS_OFF + r * (APAD * 2);
            #pragma unroll
            for (int j = 0; j < 8; j++) {
                float4 v = src[j * 8];
                *reinterpret_cast<uint2*>(dstrow + (sub + j * 8) * 8) =
                    make_uint2(packbf(v.x, v.y), packbf(v.z, v.w));
            }
        }
    }
    __syncthreads();

    const int m0 = wid * 16;
    float c[32][4];
    #pragma unroll
    for (int j = 0; j < 32; j++) { c[j][0] = c[j][1] = c[j][2] = c[j][3] = 0.f; }

    const uint32_t a_addr = sb + AS_OFF + (m0 + (lane & 15)) * (APAD * 2) + (lane >> 4) * 16;
    const uint32_t b_addr = sb + BS_OFF + (lane & 7) * (APAD * 2) + ((lane >> 3) & 1) * 16;

    for (int k = 0; k < 16; k++) {
        uint32_t a[4];
        ldsm_x4(a, a_addr + k * 32);
        #pragma unroll
        for (int j = 0; j < 32; j++) {
            uint32_t b[2];
            ldsm_x2(b, b_addr + j * 8 * (APAD * 2) + k * 32);
            mma_bf16(c[j], a, b);
        }
    }

    float* outp = g_xw + (size_t)t * (B_DIM * U_DIM);
    const int r0 = m0 + (lane >> 2), c0 = (lane & 3) * 2;
    #pragma unroll
    for (int j = 0; j < 32; j++) {
        const int col = j * 8 + c0;
        *reinterpret_cast<float2*>(outp + r0 * U_DIM + col)       = make_float2(c[j][0], c[j][1]);
        *reinterpret_cast<float2*>(outp + (r0 + 8) * U_DIM + col) = make_float2(c[j][2], c[j][3]);
    }
}

// ---------------- Kernel 2: cluster-4 tensor-core recurrence ----------------
// 32 CTAs = 8 clusters of 4. Cluster handles one 16-row batch tile; CTA rank r
// owns u-slice [64r, 64r+64). C'[u,b] = sum_k U[u,k] h[b,k]:
//   A = U (REGISTERS, loaded once: 64 regs/warp), B = h via ldsm (bf16 smem).
// Warp (uw = wid>>1, bw = wid&1): u-tile 16, b-tile 8 -> 16 HMMA/step.
// Epilogue: +xw, tanh, pack bf16, movmatrix.trans (C'(u,b) -> h(b,u)),
// store to own + 3 peer CTAs' h buffers via st.shared::cluster (DSMEM).
// Step sync: barrier.cluster arrive/wait split around xw prefetch.

static constexpr int HSTRIDE = 528;                  // bytes per b-row (264 bf16)
static constexpr int HBUF    = 16 * HSTRIDE;         // 8448 per buffer

__global__ void __launch_bounds__(256, 1) __cluster_dims__(4, 1, 1)
rnn_kernel(const float* __restrict__ Um, const float* __restrict__ W1,
           const float* __restrict__ b1, const float* __restrict__ W2,
           const float* __restrict__ b2, float* __restrict__ out) {
    __shared__ __align__(16) char hbuf[2 * HBUF];
    __shared__ __align__(16) float hfin[16 * 256];
    __shared__ float hid[16 * 32];

    const int tid = threadIdx.x, wid = tid >> 5, lane = tid & 31;
    const int rank  = blockIdx.x & 3;
    const int btile = (blockIdx.x >> 2) * 16;
    const int uw = wid >> 1, bw = wid & 1;
    const int u0g = rank * 64 + uw * 16;     // global u base of this warp's tile
    const int b8  = bw * 8;                  // local b base
    const int r = lane >> 2, q = lane & 3;

    // ---- U fragments into registers (once): canonical m16k16 A layout ----
    uint32_t ua[64];
    #pragma unroll
    for (int kt = 0; kt < 16; kt++) {
        const float2* p0 = reinterpret_cast<const float2*>(Um + (size_t)(u0g + r) * U_DIM + kt * 16 + 2 * q);
        const float2* p1 = reinterpret_cast<const float2*>(Um + (size_t)(u0g + r + 8) * U_DIM + kt * 16 + 2 * q);
        float2 v0 = p0[0], v1 = p1[0], v2 = p0[4], v3 = p1[4];
        ua[kt * 4 + 0] = packbf(v0.x, v0.y);   // (r,    k lo)
        ua[kt * 4 + 1] = packbf(v1.x, v1.y);   // (r+8,  k lo)
        ua[kt * 4 + 2] = packbf(v2.x, v2.y);   // (r,    k hi)
        ua[kt * 4 + 3] = packbf(v3.x, v3.y);   // (r+8,  k hi)
    }

    // zero both h buffers (h0 = 0)
    for (int i = tid; i < (2 * HBUF) / 4; i += 256)
        reinterpret_cast<uint32_t*>(hbuf)[i] = 0;

    // peer smem bases (DSMEM) + rank0's hfin
    const uint32_t hb_l = smem_u32(hbuf);
    uint32_t pb[3];
    {
        int pj = 0;
        #pragma unroll
        for (int j = 0; j < 4; j++)
            if (j != rank) {
                asm("mapa.shared::cluster.u32 %0, %1, %2;" : "=r"(pb[pj]) : "r"(hb_l), "r"(j));
                pj++;
            }
    }
    uint32_t hfin_r0;
    {
        uint32_t hf = smem_u32(hfin);
        asm("mapa.shared::cluster.u32 %0, %1, %2;" : "=r"(hfin_r0) : "r"(hf), "r"(0));
    }

    asm volatile("barrier.cluster.arrive.aligned;" ::: "memory");
    asm volatile("barrier.cluster.wait.aligned;" ::: "memory");

    // per-lane xw pointers: xw(t, b, u) with b = btile+b8+2q(+1), u = u0g+r(+8)
    const float* xw00 = g_xw + (size_t)(btile + b8 + 2 * q) * U_DIM + u0g + r;
    float xv0 = xw00[0], xv1 = xw00[256], xv2 = xw00[8], xv3 = xw00[264];

    const uint32_t rd0 = hb_l + (b8 + (lane & 7)) * HSTRIDE + (lane >> 3) * 16;
    const uint32_t so0 = (b8 + r) * HSTRIDE + (u0g + 2 * q) * 2;   // trans-store offset

    for (int t = 0; t < T_DIM; t++) {
        const uint32_t rb = rd0 + (t & 1) * HBUF;
        float aA[4] = {0.f, 0.f, 0.f, 0.f}, aB[4] = {0.f, 0.f, 0.f, 0.f};
        #pragma unroll
        for (int kb = 0; kb < 8; kb++) {                 // k32 blocks
            uint32_t bq[4];
            ldsm_x4(bq, rb + kb * 64);                   // h rows b8.., k32
            mma_bf16(aA, ua + kb * 8,     bq);           // k-tile 2kb
            mma_bf16(aB, ua + kb * 8 + 4, bq + 2);       // k-tile 2kb+1
        }
        float h0 = aA[0] + aB[0] + xv0;                  // (u0g+r,   b8+2q)
        float h1 = aA[1] + aB[1] + xv1;                  // (u0g+r,   b8+2q+1)
        float h2 = aA[2] + aB[2] + xv2;                  // (u0g+r+8, b8+2q)
        float h3 = aA[3] + aB[3] + xv3;                  // (u0g+r+8, b8+2q+1)
        asm("tanh.approx.f32 %0, %1;" : "=f"(h0) : "f"(h0));
        asm("tanh.approx.f32 %0, %1;" : "=f"(h1) : "f"(h1));
        asm("tanh.approx.f32 %0, %1;" : "=f"(h2) : "f"(h2));
        asm("tanh.approx.f32 %0, %1;" : "=f"(h3) : "f"(h3));

        if (t == T_DIM - 1) {                            // fp32 h -> rank0's hfin
            uint32_t fo = hfin_r0 + (uint32_t)(((b8 + 2 * q) * 256 + u0g + r) * 4);
            asm volatile("st.shared::cluster.b32 [%0], %1;" :: "r"(fo),           "r"(__float_as_uint(h0)));
            asm volatile("st.shared::cluster.b32 [%0], %1;" :: "r"(fo + 1024),    "r"(__float_as_uint(h1)));
            asm volatile("st.shared::cluster.b32 [%0], %1;" :: "r"(fo + 32),      "r"(__float_as_uint(h2)));
            asm volatile("st.shared::cluster.b32 [%0], %1;" :: "r"(fo + 1056),    "r"(__float_as_uint(h3)));
        }

        uint32_t m0 = packbf(h0, h1), m1 = packbf(h2, h3);
        uint32_t t0, t1;                                 // transpose (u,b) -> (b,u)
        asm("movmatrix.sync.aligned.m8n8.trans.b16 %0, %1;" : "=r"(t0) : "r"(m0));
        asm("movmatrix.sync.aligned.m8n8.trans.b16 %0, %1;" : "=r"(t1) : "r"(m1));

        const uint32_t woff = (uint32_t)(((t & 1) ^ 1) * HBUF) + so0;
        asm volatile("st.shared.b32 [%0], %1;" :: "r"(hb_l + woff),      "r"(t0));
        asm volatile("st.shared.b32 [%0], %1;" :: "r"(hb_l + woff + 16), "r"(t1));
        #pragma unroll
        for (int j = 0; j < 3; j++) {
            asm volatile("st.shared::cluster.b32 [%0], %1;" :: "r"(pb[j] + woff),      "r"(t0));
            asm volatile("st.shared::cluster.b32 [%0], %1;" :: "r"(pb[j] + woff + 16), "r"(t1));
        }

        asm volatile("barrier.cluster.arrive.aligned;" ::: "memory");
        const float* xn = xw00 + (size_t)(t + 1 < T_DIM ? t + 1 : t) * (B_DIM * U_DIM);
        xv0 = xn[0]; xv1 = xn[256]; xv2 = xn[8]; xv3 = xn[264];
        asm volatile("barrier.cluster.wait.aligned;" ::: "memory");
    }

    // ---- head on rank 0 (has full fp32 hfin) ----
    if (rank == 0) {
        #pragma unroll
        for (int it = 0; it < 2; it++) {
            const int idx = tid + it * 256, rr = idx >> 5, j = idx & 31;
            float a = b1[j];
            #pragma unroll 8
            for (int k = 0; k < 256; k++) a = fmaf(hfin[rr * 256 + k], W1[k * 32 + j], a);
            hid[rr * 32 + j] = fmaxf(a, 0.0f);
        }
        __syncthreads();
        if (tid < 16) {
            float l0 = b2[0], l1 = b2[1];
            #pragma unroll
            for (int j = 0; j < 32; j++) {
                float x = hid[tid * 32 + j];
                l0 += x * W2[j * 2 + 0];
                l1 += x * W2[j * 2 + 1];
            }
            float mx = fmaxf(l0, l1);
            float e0 = __expf(l0 - mx), e1 = __expf(l1 - mx);
            float inv = 1.0f / (e0 + e1);
            out[(btile + tid) * 2 + 0] = e0 * inv;
            out[(btile + tid) * 2 + 1] = e1 * inv;
        }
    }
}

// ---------------- launch ----------------
extern "C" void kernel_launch(void* const* d_in, const int* in_sizes, int n_in,
                              void* d_out, int out_size) {
    const int*   sentence = (const int*)  d_in[0];
    const float* emb      = (const float*)d_in[1];
    const float* W        = (const float*)d_in[2];
    const float* Um       = (const float*)d_in[3];
    const float* W1       = (const float*)d_in[4];
    const float* b1       = (const float*)d_in[5];
    const float* W2       = (const float*)d_in[6];
    const float* b2       = (const float*)d_in[7];
    float* out = (float*)d_out;

    cudaFuncSetAttribute(xw_kernel, cudaFuncAttributeMaxDynamicSharedMemorySize, XW_SMEM);

    xw_kernel<<<T_DIM, 256, XW_SMEM>>>(sentence, emb, W);
    rnn_kernel<<<B_DIM / 16 * 4, 256>>>(Um, W1, b1, W2, b2, out);
}

// round 11
// speedup vs baseline: 5.3984x; 1.3647x over previous
#include <cuda_runtime.h>
#include <cuda_bf16.h>
#include <cstdint>

#define T_DIM 512
#define B_DIM 128
#define E_DIM 256
#define U_DIM 256

// Scratch for xW[t][b][u]  (64 MB fp32 — L2-resident)
__device__ float g_xw[T_DIM * B_DIM * U_DIM];

// ---------------- helpers ----------------
__device__ __forceinline__ uint32_t smem_u32(const void* p) {
    uint32_t a;
    asm("{ .reg .u64 t; cvta.to.shared.u64 t, %1; cvt.u32.u64 %0, t; }" : "=r"(a) : "l"(p));
    return a;
}
__device__ __forceinline__ uint32_t packbf(float a, float b) {
    __nv_bfloat162 t = __floats2bfloat162_rn(a, b);   // .x -> low 16, .y -> high 16
    return *reinterpret_cast<uint32_t*>(&t);
}
__device__ __forceinline__ void ldsm_x4(uint32_t* r, uint32_t addr) {
    asm volatile("ldmatrix.sync.aligned.m8n8.x4.shared.b16 {%0,%1,%2,%3}, [%4];"
                 : "=r"(r[0]), "=r"(r[1]), "=r"(r[2]), "=r"(r[3]) : "r"(addr));
}
__device__ __forceinline__ void ldsm_x2(uint32_t* r, uint32_t addr) {
    asm volatile("ldmatrix.sync.aligned.m8n8.x2.shared.b16 {%0,%1}, [%2];"
                 : "=r"(r[0]), "=r"(r[1]) : "r"(addr));
}
__device__ __forceinline__ void mma_bf16(float* c, const uint32_t* a, const uint32_t* b) {
    asm volatile("mma.sync.aligned.m16n8k16.row.col.f32.bf16.bf16.f32 "
                 "{%0,%1,%2,%3}, {%4,%5,%6,%7}, {%8,%9}, {%0,%1,%2,%3};"
                 : "+f"(c[0]), "+f"(c[1]), "+f"(c[2]), "+f"(c[3])
                 : "r"(a[0]), "r"(a[1]), "r"(a[2]), "r"(a[3]), "r"(b[0]), "r"(b[1]));
}

// ---------------- Kernel 1: xW[t][b][u] = emb[token(b,t)] . W[u] ----------------
// One CTA per timestep t (512 CTAs, 256 threads / 8 warps), bf16 HMMA.

static constexpr int APAD = 264;                     // bf16 elems per smem row
static constexpr int AS_OFF = 0;
static constexpr int BS_OFF = 128 * APAD * 2;        // 67584
static constexpr int XW_SMEM = BS_OFF + 256 * APAD * 2;  // 202752

__global__ void __launch_bounds__(256, 1)
xw_kernel(const int* __restrict__ sentence, const float* __restrict__ emb,
          const float* __restrict__ W) {
    extern __shared__ char smem[];
    const int tid = threadIdx.x, t = blockIdx.x;
    const int wid = tid >> 5, lane = tid & 31;
    const uint32_t sb = smem_u32(smem);

    {
        const int sub = tid & 7;
        #pragma unroll
        for (int p = 0; p < 4; p++) {
            const int r = p * 32 + (tid >> 3);
            const int tok = sentence[r * T_DIM + t];
            const float4* src = reinterpret_cast<const float4*>(emb + (size_t)tok * E_DIM) + sub;
            char* dstrow = smem + AS_OFF + r * (APAD * 2);
            #pragma unroll
            for (int j = 0; j < 8; j++) {
                float4 v = src[j * 8];
                *reinterpret_cast<uint2*>(dstrow + (sub + j * 8) * 8) =
                    make_uint2(packbf(v.x, v.y), packbf(v.z, v.w));
            }
        }
    }
    {
        const int sub = tid & 7;
        #pragma unroll
        for (int p = 0; p < 8; p++) {
            const int r = p * 32 + (tid >> 3);
            const float4* src = reinterpret_cast<const float4*>(W + (size_t)r * E_DIM) + sub;
            char* dstrow = smem + BS_OFF + r * (APAD * 2);
            #pragma unroll
            for (int j = 0; j < 8; j++) {
                float4 v = src[j * 8];
                *reinterpret_cast<uint2*>(dstrow + (sub + j * 8) * 8) =
                    make_uint2(packbf(v.x, v.y), packbf(v.z, v.w));
            }
        }
    }
    __syncthreads();

    const int m0 = wid * 16;
    float c[32][4];
    #pragma unroll
    for (int j = 0; j < 32; j++) { c[j][0] = c[j][1] = c[j][2] = c[j][3] = 0.f; }

    const uint32_t a_addr = sb + AS_OFF + (m0 + (lane & 15)) * (APAD * 2) + (lane >> 4) * 16;
    const uint32_t b_addr = sb + BS_OFF + (lane & 7) * (APAD * 2) + ((lane >> 3) & 1) * 16;

    for (int k = 0; k < 16; k++) {
        uint32_t a[4];
        ldsm_x4(a, a_addr + k * 32);
        #pragma unroll
        for (int j = 0; j < 32; j++) {
            uint32_t b[2];
            ldsm_x2(b, b_addr + j * 8 * (APAD * 2) + k * 32);
            mma_bf16(c[j], a, b);
        }
    }

    float* outp = g_xw + (size_t)t * (B_DIM * U_DIM);
    const int r0 = m0 + (lane >> 2), c0 = (lane & 3) * 2;
    #pragma unroll
    for (int j = 0; j < 32; j++) {
        const int col = j * 8 + c0;
        *reinterpret_cast<float2*>(outp + r0 * U_DIM + col)       = make_float2(c[j][0], c[j][1]);
        *reinterpret_cast<float2*>(outp + (r0 + 8) * U_DIM + col) = make_float2(c[j][2], c[j][3]);
    }
}

// ---------------- Kernel 2: batch-split tensor-core recurrence ----------------
// 16 CTAs x 8 batch rows (independent — NO cross-CTA traffic), 512 threads.
// C'[u,b] = sum_k U[u,k] h[b,k]: warp wid owns u-tile [16*wid, 16*wid+16), b-tile 8.
//   A = U in REGISTERS (64 regs/warp, loaded once — zero A traffic per step),
//   B = h (bf16, smem, double-buffered) via 8 ldsm_x4; 16 HMMA in 2 interleaved
//   depth-8 chains. Epilogue: +xw, tanh, movmatrix-transpose, 2 local STS.32.
// Step sync = one __syncthreads. xw for t+1 prefetched at top of step t.

static constexpr int HSTRIDE = 528;                  // bytes per b-row (264 bf16)
static constexpr int HBUF    = 8 * HSTRIDE;          // 4224 per buffer

__global__ void __launch_bounds__(512, 1)
rnn_kernel(const float* __restrict__ Um, const float* __restrict__ W1,
           const float* __restrict__ b1, const float* __restrict__ W2,
           const float* __restrict__ b2, float* __restrict__ out) {
    __shared__ __align__(16) char hbuf[2 * HBUF];
    __shared__ __align__(16) float hfin[8 * 256];
    __shared__ float hid[8 * 32];

    const int tid = threadIdx.x, wid = tid >> 5, lane = tid & 31;
    const int b0 = blockIdx.x * 8;           // batch rows b0..b0+7
    const int u0 = wid * 16;                 // this warp's u-tile
    const int r = lane >> 2, q = lane & 3;

    // ---- U fragments into registers (once): canonical m16k16 A layout ----
    uint32_t ua[64];
    #pragma unroll
    for (int kt = 0; kt < 16; kt++) {
        const float2* p0 = reinterpret_cast<const float2*>(Um + (size_t)(u0 + r) * U_DIM + kt * 16 + 2 * q);
        const float2* p1 = reinterpret_cast<const float2*>(Um + (size_t)(u0 + r + 8) * U_DIM + kt * 16 + 2 * q);
        float2 v0 = p0[0], v1 = p1[0], v2 = p0[4], v3 = p1[4];
        ua[kt * 4 + 0] = packbf(v0.x, v0.y);   // (r,    k lo)
        ua[kt * 4 + 1] = packbf(v1.x, v1.y);   // (r+8,  k lo)
        ua[kt * 4 + 2] = packbf(v2.x, v2.y);   // (r,    k hi)
        ua[kt * 4 + 3] = packbf(v3.x, v3.y);   // (r+8,  k hi)
    }

    // zero both h buffers (h0 = 0)
    for (int i = tid; i < (2 * HBUF) / 4; i += 512)
        reinterpret_cast<uint32_t*>(hbuf)[i] = 0;
    __syncthreads();

    const uint32_t hb = smem_u32(hbuf);
    const uint32_t rd0 = hb + (lane & 7) * HSTRIDE + (lane >> 3) * 16;   // ldsm B addr
    const uint32_t so0 = r * HSTRIDE + (u0 + 2 * q) * 2;                 // trans-store

    // per-lane xw: (b0+2q, u0+r) base; +256 = b+1 row, +8 = u+8
    const float* xw00 = g_xw + (size_t)(b0 + 2 * q) * U_DIM + u0 + r;
    float xv0 = xw00[0], xv1 = xw00[256], xv2 = xw00[8], xv3 = xw00[264];

    for (int t = 0; t < T_DIM; t++) {
        // prefetch next step's xw (independent of h; L2 hits, full step to cover)
        const float* xn = xw00 + (size_t)(t + 1 < T_DIM ? t + 1 : t) * (B_DIM * U_DIM);
        const float n0 = xn[0], n1 = xn[256], n2 = xn[8], n3 = xn[264];

        const uint32_t rb = rd0 + (t & 1) * HBUF;
        float aA[4] = {0.f, 0.f, 0.f, 0.f}, aB[4] = {0.f, 0.f, 0.f, 0.f};
        #pragma unroll
        for (int kb = 0; kb < 8; kb++) {                 // k32 blocks
            uint32_t bq[4];
            ldsm_x4(bq, rb + kb * 64);                   // h rows 0..7, k32
            mma_bf16(aA, ua + kb * 8,     bq);           // k-tile 2kb   (chain A)
            mma_bf16(aB, ua + kb * 8 + 4, bq + 2);       // k-tile 2kb+1 (chain B)
        }
        float h0 = aA[0] + aB[0] + xv0;                  // (u0+r,   b0+2q)
        float h1 = aA[1] + aB[1] + xv1;                  // (u0+r,   b0+2q+1)
        float h2 = aA[2] + aB[2] + xv2;                  // (u0+r+8, b0+2q)
        float h3 = aA[3] + aB[3] + xv3;                  // (u0+r+8, b0+2q+1)
        asm("tanh.approx.f32 %0, %1;" : "=f"(h0) : "f"(h0));
        asm("tanh.approx.f32 %0, %1;" : "=f"(h1) : "f"(h1));
        asm("tanh.approx.f32 %0, %1;" : "=f"(h2) : "f"(h2));
        asm("tanh.approx.f32 %0, %1;" : "=f"(h3) : "f"(h3));

        if (t == T_DIM - 1) {                            // fp32 h for the head
            hfin[(2 * q) * 256 + u0 + r]         = h0;
            hfin[(2 * q + 1) * 256 + u0 + r]     = h1;
            hfin[(2 * q) * 256 + u0 + r + 8]     = h2;
            hfin[(2 * q + 1) * 256 + u0 + r + 8] = h3;
        }

        uint32_t m0 = packbf(h0, h1), m1 = packbf(h2, h3);
        uint32_t t0, t1;                                 // transpose (u,b) -> (b,u)
        asm("movmatrix.sync.aligned.m8n8.trans.b16 %0, %1;" : "=r"(t0) : "r"(m0));
        asm("movmatrix.sync.aligned.m8n8.trans.b16 %0, %1;" : "=r"(t1) : "r"(m1));

        const uint32_t wa = hb + (uint32_t)(((t & 1) ^ 1) * HBUF) + so0;
        asm volatile("st.shared.b32 [%0], %1;" :: "r"(wa),      "r"(t0));
        asm volatile("st.shared.b32 [%0], %1;" :: "r"(wa + 16), "r"(t1));

        xv0 = n0; xv1 = n1; xv2 = n2; xv3 = n3;
        __syncthreads();
    }

    // ---- head: hidden = relu(hfin @ W1 + b1); logits -> softmax ----
    if (tid < 256) {                       // 8 rows x 32 units
        const int rr = tid >> 5, j = tid & 31;
        float a = b1[j];
        #pragma unroll 8
        for (int k = 0; k < 256; k++) a = fmaf(hfin[rr * 256 + k], W1[k * 32 + j], a);
        hid[rr * 32 + j] = fmaxf(a, 0.0f);
    }
    __syncthreads();
    if (tid < 8) {
        float l0 = b2[0], l1 = b2[1];
        #pragma unroll
        for (int j = 0; j < 32; j++) {
            float x = hid[tid * 32 + j];
            l0 += x * W2[j * 2 + 0];
            l1 += x * W2[j * 2 + 1];
        }
        float mx = fmaxf(l0, l1);
        float e0 = __expf(l0 - mx), e1 = __expf(l1 - mx);
        float inv = 1.0f / (e0 + e1);
        out[(b0 + tid) * 2 + 0] = e0 * inv;
        out[(b0 + tid) * 2 + 1] = e1 * inv;
    }
}

// ---------------- launch ----------------
extern "C" void kernel_launch(void* const* d_in, const int* in_sizes, int n_in,
                              void* d_out, int out_size) {
    const int*   sentence = (const int*)  d_in[0];
    const float* emb      = (const float*)d_in[1];
    const float* W        = (const float*)d_in[2];
    const float* Um       = (const float*)d_in[3];
    const float* W1       = (const float*)d_in[4];
    const float* b1       = (const float*)d_in[5];
    const float* W2       = (const float*)d_in[6];
    const float* b2       = (const float*)d_in[7];
    float* out = (float*)d_out;

    cudaFuncSetAttribute(xw_kernel, cudaFuncAttributeMaxDynamicSharedMemorySize, XW_SMEM);

    xw_kernel<<<T_DIM, 256, XW_SMEM>>>(sentence, emb, W);
    rnn_kernel<<<B_DIM / 8, 512>>>(Um, W1, b1, W2, b2, out);
}

// round 12
// speedup vs baseline: 5.7410x; 1.0635x over previous
#include <cuda_runtime.h>
#include <cuda_bf16.h>
#include <cstdint>

#define T_DIM 512
#define B_DIM 128
#define E_DIM 256
#define U_DIM 256

// Scratch for xW[t][b][u]  (64 MB fp32 — L2-resident)
__device__ float g_xw[T_DIM * B_DIM * U_DIM];

// ---------------- helpers ----------------
__device__ __forceinline__ uint32_t smem_u32(const void* p) {
    uint32_t a;
    asm("{ .reg .u64 t; cvta.to.shared.u64 t, %1; cvt.u32.u64 %0, t; }" : "=r"(a) : "l"(p));
    return a;
}
__device__ __forceinline__ uint32_t packbf(float a, float b) {
    __nv_bfloat162 t = __floats2bfloat162_rn(a, b);   // .x -> low 16, .y -> high 16
    return *reinterpret_cast<uint32_t*>(&t);
}
__device__ __forceinline__ void ldsm_x4(uint32_t* r, uint32_t addr) {
    asm volatile("ldmatrix.sync.aligned.m8n8.x4.shared.b16 {%0,%1,%2,%3}, [%4];"
                 : "=r"(r[0]), "=r"(r[1]), "=r"(r[2]), "=r"(r[3]) : "r"(addr));
}
__device__ __forceinline__ void ldsm_x2(uint32_t* r, uint32_t addr) {
    asm volatile("ldmatrix.sync.aligned.m8n8.x2.shared.b16 {%0,%1}, [%2];"
                 : "=r"(r[0]), "=r"(r[1]) : "r"(addr));
}
__device__ __forceinline__ void mma_bf16(float* c, const uint32_t* a, const uint32_t* b) {
    asm volatile("mma.sync.aligned.m16n8k16.row.col.f32.bf16.bf16.f32 "
                 "{%0,%1,%2,%3}, {%4,%5,%6,%7}, {%8,%9}, {%0,%1,%2,%3};"
                 : "+f"(c[0]), "+f"(c[1]), "+f"(c[2]), "+f"(c[3])
                 : "r"(a[0]), "r"(a[1]), "r"(a[2]), "r"(a[3]), "r"(b[0]), "r"(b[1]));
}
__device__ __forceinline__ void cpasync16(uint32_t dst, const void* src) {
    asm volatile("cp.async.ca.shared.global [%0], [%1], 16;" :: "r"(dst), "l"(src) : "memory");
}

// ---------------- Kernel 1: xW[t][b][u] = emb[token(b,t)] . W[u] ----------------
// One CTA per timestep t (512 CTAs, 256 threads / 8 warps), bf16 HMMA.

static constexpr int APAD = 264;                     // bf16 elems per smem row
static constexpr int AS_OFF = 0;
static constexpr int BS_OFF = 128 * APAD * 2;        // 67584
static constexpr int XW_SMEM = BS_OFF + 256 * APAD * 2;  // 202752

__global__ void __launch_bounds__(256, 1)
xw_kernel(const int* __restrict__ sentence, const float* __restrict__ emb,
          const float* __restrict__ W) {
    extern __shared__ char smem[];
    const int tid = threadIdx.x, t = blockIdx.x;
    const int wid = tid >> 5, lane = tid & 31;
    const uint32_t sb = smem_u32(smem);

    {
        const int sub = tid & 7;
        #pragma unroll
        for (int p = 0; p < 4; p++) {
            const int r = p * 32 + (tid >> 3);
            const int tok = sentence[r * T_DIM + t];
            const float4* src = reinterpret_cast<const float4*>(emb + (size_t)tok * E_DIM) + sub;
            char* dstrow = smem + AS_OFF + r * (APAD * 2);
            #pragma unroll
            for (int j = 0; j < 8; j++) {
                float4 v = src[j * 8];
                *reinterpret_cast<uint2*>(dstrow + (sub + j * 8) * 8) =
                    make_uint2(packbf(v.x, v.y), packbf(v.z, v.w));
            }
        }
    }
    {
        const int sub = tid & 7;
        #pragma unroll
        for (int p = 0; p < 8; p++) {
            const int r = p * 32 + (tid >> 3);
            const float4* src = reinterpret_cast<const float4*>(W + (size_t)r * E_DIM) + sub;
            char* dstrow = smem + BS_OFF + r * (APAD * 2);
            #pragma unroll
            for (int j = 0; j < 8; j++) {
                float4 v = src[j * 8];
                *reinterpret_cast<uint2*>(dstrow + (sub + j * 8) * 8) =
                    make_uint2(packbf(v.x, v.y), packbf(v.z, v.w));
            }
        }
    }
    __syncthreads();

    const int m0 = wid * 16;
    float c[32][4];
    #pragma unroll
    for (int j = 0; j < 32; j++) { c[j][0] = c[j][1] = c[j][2] = c[j][3] = 0.f; }

    const uint32_t a_addr = sb + AS_OFF + (m0 + (lane & 15)) * (APAD * 2) + (lane >> 4) * 16;
    const uint32_t b_addr = sb + BS_OFF + (lane & 7) * (APAD * 2) + ((lane >> 3) & 1) * 16;

    for (int k = 0; k < 16; k++) {
        uint32_t a[4];
        ldsm_x4(a, a_addr + k * 32);
        #pragma unroll
        for (int j = 0; j < 32; j++) {
            uint32_t b[2];
            ldsm_x2(b, b_addr + j * 8 * (APAD * 2) + k * 32);
            mma_bf16(c[j], a, b);
        }
    }

    float* outp = g_xw + (size_t)t * (B_DIM * U_DIM);
    const int r0 = m0 + (lane >> 2), c0 = (lane & 3) * 2;
    #pragma unroll
    for (int j = 0; j < 32; j++) {
        const int col = j * 8 + c0;
        *reinterpret_cast<float2*>(outp + r0 * U_DIM + col)       = make_float2(c[j][0], c[j][1]);
        *reinterpret_cast<float2*>(outp + (r0 + 8) * U_DIM + col) = make_float2(c[j][2], c[j][3]);
    }
}

// ---------------- Kernel 2: batch-split tensor-core recurrence ----------------
// 16 CTAs x 8 batch rows, 512 threads. Warp wid owns u-tile [16*wid,16*wid+16),
// all 8 b-rows. A = U in registers (64 regs, loaded once); B = h (bf16 smem,
// double-buffered) via 8 ldsm_x4; 16 HMMA in FOUR depth-4 chains.
// xw staged per-step into double-buffered smem via cp.async (no LDG in loop).

static constexpr int HSTRIDE = 528;                  // bytes per b-row (264 bf16)
static constexpr int HBUF    = 8 * HSTRIDE;          // 4224 per buffer
static constexpr int XWTILE  = 8 * 256 * 4;          // 8192 per stage buffer

__global__ void __launch_bounds__(512, 1)
rnn_kernel(const float* __restrict__ Um, const float* __restrict__ W1,
           const float* __restrict__ b1, const float* __restrict__ W2,
           const float* __restrict__ b2, float* __restrict__ out) {
    __shared__ __align__(16) char hbuf[2 * HBUF];
    __shared__ __align__(16) float xws[2 * 8 * 256];
    __shared__ __align__(16) float hfin[8 * 256];
    __shared__ float hid[8 * 32];

    const int tid = threadIdx.x, wid = tid >> 5, lane = tid & 31;
    const int b0 = blockIdx.x * 8;           // batch rows b0..b0+7
    const int u0 = wid * 16;                 // this warp's u-tile
    const int r = lane >> 2, q = lane & 3;

    // ---- U fragments into registers (once): canonical m16k16 A layout ----
    uint32_t ua[64];
    #pragma unroll
    for (int kt = 0; kt < 16; kt++) {
        const float2* p0 = reinterpret_cast<const float2*>(Um + (size_t)(u0 + r) * U_DIM + kt * 16 + 2 * q);
        const float2* p1 = reinterpret_cast<const float2*>(Um + (size_t)(u0 + r + 8) * U_DIM + kt * 16 + 2 * q);
        float2 v0 = p0[0], v1 = p1[0], v2 = p0[4], v3 = p1[4];
        ua[kt * 4 + 0] = packbf(v0.x, v0.y);   // (r,    k lo)
        ua[kt * 4 + 1] = packbf(v1.x, v1.y);   // (r+8,  k lo)
        ua[kt * 4 + 2] = packbf(v2.x, v2.y);   // (r,    k hi)
        ua[kt * 4 + 3] = packbf(v3.x, v3.y);   // (r+8,  k hi)
    }

    // zero both h buffers (h0 = 0)
    for (int i = tid; i < (2 * HBUF) / 4; i += 512)
        reinterpret_cast<uint32_t*>(hbuf)[i] = 0;

    // prologue: stage xw(t=0) into buffer 0
    const uint32_t xw_smem = smem_u32(xws);
    const char* xw_gsrc = reinterpret_cast<const char*>(g_xw + (size_t)b0 * U_DIM) + tid * 16;
    cpasync16(xw_smem + tid * 16, xw_gsrc);
    asm volatile("cp.async.commit_group;" ::: "memory");
    asm volatile("cp.async.wait_group 0;" ::: "memory");
    __syncthreads();

    const uint32_t hb = smem_u32(hbuf);
    const uint32_t rd0 = hb + (lane & 7) * HSTRIDE + (lane >> 3) * 16;   // ldsm B addr
    const uint32_t so0 = r * HSTRIDE + (u0 + 2 * q) * 2;                 // trans-store

    // xv LDS offsets within a stage buffer (floats): (2q, u0+r) etc.
    const int xo = (2 * q) * 256 + u0 + r;

    for (int t = 0; t < T_DIM; t++) {
        // kick off staging of xw(t+1) into the other buffer
        if (t + 1 < T_DIM) {
            const char* src = reinterpret_cast<const char*>(
                g_xw + (size_t)(t + 1) * (B_DIM * U_DIM) + (size_t)b0 * U_DIM) + tid * 16;
            cpasync16(xw_smem + ((t + 1) & 1) * XWTILE + tid * 16, src);
        }
        asm volatile("cp.async.commit_group;" ::: "memory");

        // read this step's xw from smem stage (completed + barriered last step)
        const float* xs = xws + (t & 1) * (8 * 256) + xo;
        const float xv0 = xs[0], xv1 = xs[256], xv2 = xs[8], xv3 = xs[264];

        const uint32_t rb = rd0 + (t & 1) * HBUF;
        float aA0[4] = {0.f, 0.f, 0.f, 0.f}, aA1[4] = {0.f, 0.f, 0.f, 0.f};
        float aB0[4] = {0.f, 0.f, 0.f, 0.f}, aB1[4] = {0.f, 0.f, 0.f, 0.f};
        #pragma unroll
        for (int kb = 0; kb < 4; kb++) {                 // two k32 blocks per iter
            uint32_t bq[4], bq2[4];
            ldsm_x4(bq,  rb + (2 * kb) * 64);
            ldsm_x4(bq2, rb + (2 * kb + 1) * 64);
            mma_bf16(aA0, ua + (2 * kb) * 8,     bq);        // chain A0 (depth 4)
            mma_bf16(aB0, ua + (2 * kb) * 8 + 4, bq + 2);    // chain B0
            mma_bf16(aA1, ua + (2 * kb + 1) * 8,     bq2);   // chain A1
            mma_bf16(aB1, ua + (2 * kb + 1) * 8 + 4, bq2 + 2);// chain B1
        }
        float h0 = (aA0[0] + aB0[0]) + (aA1[0] + aB1[0]) + xv0;  // (u0+r,   b+2q)
        float h1 = (aA0[1] + aB0[1]) + (aA1[1] + aB1[1]) + xv1;  // (u0+r,   b+2q+1)
        float h2 = (aA0[2] + aB0[2]) + (aA1[2] + aB1[2]) + xv2;  // (u0+r+8, b+2q)
        float h3 = (aA0[3] + aB0[3]) + (aA1[3] + aB1[3]) + xv3;  // (u0+r+8, b+2q+1)
        asm("tanh.approx.f32 %0, %1;" : "=f"(h0) : "f"(h0));
        asm("tanh.approx.f32 %0, %1;" : "=f"(h1) : "f"(h1));
        asm("tanh.approx.f32 %0, %1;" : "=f"(h2) : "f"(h2));
        asm("tanh.approx.f32 %0, %1;" : "=f"(h3) : "f"(h3));

        if (t == T_DIM - 1) {                            // fp32 h for the head
            hfin[(2 * q) * 256 + u0 + r]         = h0;
            hfin[(2 * q + 1) * 256 + u0 + r]     = h1;
            hfin[(2 * q) * 256 + u0 + r + 8]     = h2;
            hfin[(2 * q + 1) * 256 + u0 + r + 8] = h3;
        }

        uint32_t m0 = packbf(h0, h1), m1 = packbf(h2, h3);
        uint32_t t0, t1;                                 // transpose (u,b) -> (b,u)
        asm("movmatrix.sync.aligned.m8n8.trans.b16 %0, %1;" : "=r"(t0) : "r"(m0));
        asm("movmatrix.sync.aligned.m8n8.trans.b16 %0, %1;" : "=r"(t1) : "r"(m1));

        const uint32_t wa = hb + (uint32_t)(((t & 1) ^ 1) * HBUF) + so0;
        asm volatile("st.shared.b32 [%0], %1;" :: "r"(wa),      "r"(t0));
        asm volatile("st.shared.b32 [%0], %1;" :: "r"(wa + 16), "r"(t1));

        asm volatile("cp.async.wait_group 0;" ::: "memory");  // xw(t+1) landed
        __syncthreads();                                      // h(t+1) + xw visible
    }

    // ---- head: hidden = relu(hfin @ W1 + b1); logits -> softmax ----
    if (tid < 256) {                       // 8 rows x 32 units
        const int rr = tid >> 5, j = tid & 31;
        float a = b1[j];
        #pragma unroll 8
        for (int k = 0; k < 256; k++) a = fmaf(hfin[rr * 256 + k], W1[k * 32 + j], a);
        hid[rr * 32 + j] = fmaxf(a, 0.0f);
    }
    __syncthreads();
    if (tid < 8) {
        float l0 = b2[0], l1 = b2[1];
        #pragma unroll
        for (int j = 0; j < 32; j++) {
            float x = hid[tid * 32 + j];
            l0 += x * W2[j * 2 + 0];
            l1 += x * W2[j * 2 + 1];
        }
        float mx = fmaxf(l0, l1);
        float e0 = __expf(l0 - mx), e1 = __expf(l1 - mx);
        float inv = 1.0f / (e0 + e1);
        out[(b0 + tid) * 2 + 0] = e0 * inv;
        out[(b0 + tid) * 2 + 1] = e1 * inv;
    }
}

// ---------------- launch ----------------
extern "C" void kernel_launch(void* const* d_in, const int* in_sizes, int n_in,
                              void* d_out, int out_size) {
    const int*   sentence = (const int*)  d_in[0];
    const float* emb      = (const float*)d_in[1];
    const float* W        = (const float*)d_in[2];
    const float* Um       = (const float*)d_in[3];
    const float* W1       = (const float*)d_in[4];
    const float* b1       = (const float*)d_in[5];
    const float* W2       = (const float*)d_in[6];
    const float* b2       = (const float*)d_in[7];
    float* out = (float*)d_out;

    cudaFuncSetAttribute(xw_kernel, cudaFuncAttributeMaxDynamicSharedMemorySize, XW_SMEM);

    xw_kernel<<<T_DIM, 256, XW_SMEM>>>(sentence, emb, W);
    rnn_kernel<<<B_DIM / 8, 512>>>(Um, W1, b1, W2, b2, out);
}